// round 14
// baseline (speedup 1.0000x reference)
#include <cuda_runtime.h>
#include <math.h>
#include <stdint.h>

// ---------------- problem constants ----------------
#define KD   4
#define BB   2
#define LL   784
#define DMQ  384
#define DIN  768
#define DS   16
#define DTR  24
#define NE   56
#define MROWS (BB*LL)   // 1568
#define KSPLIT 4

// ---------------- scratch ----------------
__device__ __align__(16) float g_xz   [BB*LL*2*DIN];
__device__ __align__(16) float g_convT[KD*BB*LL*DIN];
__device__ __align__(16) float g_zsT  [KD*BB*LL*DIN];
__device__ __align__(16) float g_xdblp[KSPLIT*KD*BB*LL*NE];
__device__ __align__(16) float g_xdbl [KD*BB*LL*NE];
__device__ __align__(16) float g_delta[KD*BB*LL*DIN];
__device__ __align__(16) float g_yT   [KD*BB*LL*DIN];
__device__ __align__(16) float g_gpart[KD*BB*28*DIN];
__device__ __align__(16) float g_attn [KD*BB*DIN];
__device__ __align__(16) float g_s    [BB*LL*DIN];

// forward scan map: t -> l
__device__ __forceinline__ int scan_map_f(int k, int t) {
    if (k == 0) return t;
    if (k == 1) { int wq = t / 28; int hq = t - wq * 28; return hq * 28 + wq; }
    if (k == 3) t = 783 - t;
    int hg = t / 196; int r  = t - hg * 196;
    int wg = r / 49;  int r2 = r - wg * 49;
    int i  = r2 / 7;  int j  = r2 - i * 7;
    return (hg * 7 + i) * 28 + (wg * 7 + j);
}
// inverse map: l -> t
__device__ __forceinline__ int inv_map_f(int k, int l) {
    if (k == 0) return l;
    if (k == 1) { int lr = l / 28; int lc = l - lr * 28; return lc * 28 + lr; }
    int lr = l / 28, lc = l - (l / 28) * 28;
    int t = (lr / 7) * 196 + (lc / 7) * 49 + (lr % 7) * 7 + (lc % 7);
    return (k == 3) ? 783 - t : t;
}

__device__ __forceinline__ float siluf(float v) { return v / (1.f + __expf(-v)); }

__device__ __forceinline__ float tf32r(float x) {
    uint32_t r;
    asm("cvt.rna.tf32.f32 %0, %1;" : "=r"(r) : "f"(x));
    return __uint_as_float(r);
}

__device__ __forceinline__ void mma_tf32(float* c, const uint32_t* a, const uint32_t* b) {
    asm volatile(
        "mma.sync.aligned.m16n8k8.row.col.f32.tf32.tf32.f32 "
        "{%0,%1,%2,%3}, {%4,%5,%6,%7}, {%8,%9}, {%0,%1,%2,%3};"
        : "+f"(c[0]), "+f"(c[1]), "+f"(c[2]), "+f"(c[3])
        : "r"(a[0]), "r"(a[1]), "r"(a[2]), "r"(a[3]), "r"(b[0]), "r"(b[1]));
}

// ============ tf32 GEMM: C[m][n] = sum_k A[m][k]*W[n][k] ===================
__device__ __forceinline__ void gemm_tf32_body(
    const float* __restrict__ A, const float* __restrict__ W,
    float* __restrict__ C, int M, int N, int K)
{
    __shared__ float As[2][16][136];
    __shared__ float Ws[2][16][72];
    int m0 = blockIdx.y * 128, n0 = blockIdx.x * 64;
    int tid = threadIdx.x, lane = tid & 31, wid = tid >> 5;
    int wm = (wid & 3) * 32, wn = (wid >> 2) * 32;
    int g = lane >> 2, tg = lane & 3;

    int ar = tid >> 1, ak = (tid & 1) * 8;
    int wr = tid >> 2, wk = (tid & 3) * 4;
    const float* Ap = A + (size_t)(m0 + ar) * K + ak;
    const float* Wp = W + (size_t)(n0 + wr) * K + wk;
    bool aval = (m0 + ar) < M;

    {
        float4 v0 = make_float4(0.f,0.f,0.f,0.f), v1 = v0;
        if (aval) { v0 = *(const float4*)Ap; v1 = *(const float4*)(Ap + 4); }
        As[0][ak+0][ar]=tf32r(v0.x); As[0][ak+1][ar]=tf32r(v0.y);
        As[0][ak+2][ar]=tf32r(v0.z); As[0][ak+3][ar]=tf32r(v0.w);
        As[0][ak+4][ar]=tf32r(v1.x); As[0][ak+5][ar]=tf32r(v1.y);
        As[0][ak+6][ar]=tf32r(v1.z); As[0][ak+7][ar]=tf32r(v1.w);
        float4 w = *(const float4*)Wp;
        Ws[0][wk+0][wr]=tf32r(w.x); Ws[0][wk+1][wr]=tf32r(w.y);
        Ws[0][wk+2][wr]=tf32r(w.z); Ws[0][wk+3][wr]=tf32r(w.w);
    }
    __syncthreads();

    float acc[2][4][4] = {};
    int buf = 0;
    for (int k0 = 0; k0 < K; k0 += 16) {
        if (k0 + 16 < K) {
            int nb = buf ^ 1;
            float4 v0 = make_float4(0.f,0.f,0.f,0.f), v1 = v0;
            if (aval) { v0 = *(const float4*)(Ap + k0 + 16); v1 = *(const float4*)(Ap + k0 + 20); }
            As[nb][ak+0][ar]=tf32r(v0.x); As[nb][ak+1][ar]=tf32r(v0.y);
            As[nb][ak+2][ar]=tf32r(v0.z); As[nb][ak+3][ar]=tf32r(v0.w);
            As[nb][ak+4][ar]=tf32r(v1.x); As[nb][ak+5][ar]=tf32r(v1.y);
            As[nb][ak+6][ar]=tf32r(v1.z); As[nb][ak+7][ar]=tf32r(v1.w);
            float4 w = *(const float4*)(Wp + k0 + 16);
            Ws[nb][wk+0][wr]=tf32r(w.x); Ws[nb][wk+1][wr]=tf32r(w.y);
            Ws[nb][wk+2][wr]=tf32r(w.z); Ws[nb][wk+3][wr]=tf32r(w.w);
        }
        #pragma unroll
        for (int ks = 0; ks < 16; ks += 8) {
            uint32_t a[2][4], b[4][2];
            #pragma unroll
            for (int i = 0; i < 2; i++) {
                int mb = wm + i * 16;
                a[i][0] = __float_as_uint(As[buf][ks+tg  ][mb + g    ]);
                a[i][1] = __float_as_uint(As[buf][ks+tg  ][mb + g + 8]);
                a[i][2] = __float_as_uint(As[buf][ks+tg+4][mb + g    ]);
                a[i][3] = __float_as_uint(As[buf][ks+tg+4][mb + g + 8]);
            }
            #pragma unroll
            for (int j = 0; j < 4; j++) {
                int nb2 = wn + j * 8;
                b[j][0] = __float_as_uint(Ws[buf][ks+tg  ][nb2 + g]);
                b[j][1] = __float_as_uint(Ws[buf][ks+tg+4][nb2 + g]);
            }
            #pragma unroll
            for (int i = 0; i < 2; i++)
                #pragma unroll
                for (int j = 0; j < 4; j++)
                    mma_tf32(acc[i][j], a[i], b[j]);
        }
        __syncthreads();
        buf ^= 1;
    }

    #pragma unroll
    for (int i = 0; i < 2; i++) {
        int m = m0 + wm + i * 16 + g;
        #pragma unroll
        for (int j = 0; j < 4; j++) {
            int n = n0 + wn + j * 8 + 2 * tg;
            if (m < M)
                *(float2*)(C + (size_t)m * N + n) = make_float2(acc[i][j][0], acc[i][j][1]);
            if (m + 8 < M)
                *(float2*)(C + (size_t)(m + 8) * N + n) = make_float2(acc[i][j][2], acc[i][j][3]);
        }
    }
}

__global__ __launch_bounds__(256) void gemm_in_proj(const float* __restrict__ A,
                                                    const float* __restrict__ W) {
    gemm_tf32_body(A, W, g_xz, MROWS, 2 * DIN, DMQ);
}
__global__ __launch_bounds__(256) void gemm_out_proj(const float* __restrict__ W,
                                                     float* __restrict__ C) {
    gemm_tf32_body(g_s, W, C, MROWS, DMQ, DIN);
}

// ============ gather + depthwise conv + SiLU, and silu(z) in t-order =======
__global__ void conv_z_kernel(const float* __restrict__ conv_w,
                              const float* __restrict__ conv_b)
{
    int kb = blockIdx.z; int k = kb >> 1; int b = kb & 1;
    int t0 = blockIdx.x * 32; int d0 = blockIdx.y * 32;
    __shared__ float xs[35][33];
    __shared__ float zsm[32][33];
    int tid = threadIdx.y * 32 + threadIdx.x;

    for (int idx = tid; idx < 35*32; idx += 256) {
        int r = idx >> 5; int dd = idx & 31;
        int t = t0 - 3 + r;
        float v = 0.f;
        if (t >= 0 && t < LL) {
            int l = scan_map_f(k, t);
            v = g_xz[((size_t)(b*LL + l))*(2*DIN) + d0 + dd];
        }
        xs[r][dd] = v;
    }
    for (int idx = tid; idx < 32*32; idx += 256) {
        int r = idx >> 5; int dd = idx & 31;
        int t = t0 + r;
        float v = 0.f;
        if (t < LL) {
            int l = scan_map_f(k, t);
            v = g_xz[((size_t)(b*LL + l))*(2*DIN) + DIN + d0 + dd];
        }
        zsm[r][dd] = v;
    }
    __syncthreads();

    int dloc = threadIdx.x;
    int d = d0 + dloc;
    float4 w4 = *(const float4*)(conv_w + ((size_t)k*DIN + d)*4);
    float bset = conv_b[k*DIN + d];
    #pragma unroll
    for (int s = 0; s < 4; s++) {
        int tloc = threadIdx.y * 4 + s;
        int t = t0 + tloc;
        if (t < LL) {
            float acc = bset;
            acc = fmaf(w4.x, xs[tloc+0][dloc], acc);
            acc = fmaf(w4.y, xs[tloc+1][dloc], acc);
            acc = fmaf(w4.z, xs[tloc+2][dloc], acc);
            acc = fmaf(w4.w, xs[tloc+3][dloc], acc);
            size_t off = ((size_t)kb*LL + t)*DIN + d;
            g_convT[off] = siluf(acc);
            g_zsT[off]   = siluf(zsm[tloc][dloc]);
        }
    }
}

// ============ x_dbl GEMM split-K ===========================================
__global__ __launch_bounds__(256) void gemm_xdbl(const float* __restrict__ xpw)
{
    int kb = blockIdx.z; int k = kb >> 1;
    int kc = blockIdx.x;
    const float* A = g_convT + (size_t)kb*LL*DIN;
    const float* W = xpw + (size_t)k*NE*DIN;
    float* C = g_xdblp + (size_t)kc*(KD*BB*LL*NE) + (size_t)kb*LL*NE;
    __shared__ float As[16][68];
    __shared__ float Ws[16][68];
    int m0 = blockIdx.y * 64;
    int tid = threadIdx.x;
    int lrow = tid >> 2; int lcol = (tid & 3)*4;
    int tx = tid & 15, ty = tid >> 4;
    float acc[4][4] = {};
    int kbeg = kc * 192, kend = kbeg + 192;
    for (int k0 = kbeg; k0 < kend; k0 += 16) {
        float4 av = make_float4(0.f,0.f,0.f,0.f);
        int m = m0 + lrow;
        if (m < LL) av = *(const float4*)(A + (size_t)m*DIN + k0 + lcol);
        As[lcol+0][lrow]=av.x; As[lcol+1][lrow]=av.y; As[lcol+2][lrow]=av.z; As[lcol+3][lrow]=av.w;
        float4 wv = make_float4(0.f,0.f,0.f,0.f);
        if (lrow < NE) wv = *(const float4*)(W + (size_t)lrow*DIN + k0 + lcol);
        Ws[lcol+0][lrow]=wv.x; Ws[lcol+1][lrow]=wv.y; Ws[lcol+2][lrow]=wv.z; Ws[lcol+3][lrow]=wv.w;
        __syncthreads();
        #pragma unroll
        for (int kk = 0; kk < 16; kk++) {
            float4 a = *(const float4*)&As[kk][ty*4];
            float4 w = *(const float4*)&Ws[kk][tx*4];
            float aa[4]={a.x,a.y,a.z,a.w}, ww[4]={w.x,w.y,w.z,w.w};
            #pragma unroll
            for (int i=0;i<4;i++)
                #pragma unroll
                for (int j=0;j<4;j++)
                    acc[i][j] = fmaf(aa[i], ww[j], acc[i][j]);
        }
        __syncthreads();
    }
    if (tx < 14) {
        #pragma unroll
        for (int i = 0; i < 4; i++) {
            int m = m0 + ty*4 + i;
            if (m < LL)
                #pragma unroll
                for (int j = 0; j < 4; j++)
                    C[(size_t)m*NE + tx*4 + j] = acc[i][j];
        }
    }
}

__global__ void xdbl_reduce() {
    int idx = blockIdx.x * 256 + threadIdx.x;
    if (idx >= KD*BB*LL*NE) return;
    float s = 0.f;
    #pragma unroll
    for (int kc = 0; kc < KSPLIT; kc++)
        s += g_xdblp[(size_t)kc*(KD*BB*LL*NE) + idx];
    g_xdbl[idx] = s;
}

// ============ delta GEMM + fast softplus ===================================
__global__ __launch_bounds__(256) void gemm_delta(const float* __restrict__ dtw,
                                                  const float* __restrict__ dtb)
{
    int kb = blockIdx.z; int k = kb >> 1;
    const float* A = g_xdbl + (size_t)kb*LL*NE;
    const float* W = dtw + (size_t)k*DIN*DTR;
    float* C = g_delta + (size_t)kb*LL*DIN;
    __shared__ float As[16][68];
    __shared__ float Ws[16][68];
    int m0 = blockIdx.y * 64, n0 = blockIdx.x * 64;
    int tid = threadIdx.x;
    int lrow = tid >> 2; int lcol = (tid & 3)*4;
    int tx = tid & 15, ty = tid >> 4;
    float acc[4][4] = {};
    for (int k0 = 0; k0 < 32; k0 += 16) {
        float4 av = make_float4(0.f,0.f,0.f,0.f);
        int m = m0 + lrow;
        if (m < LL) av = *(const float4*)(A + (size_t)m*NE + k0 + lcol);
        As[lcol+0][lrow]=av.x; As[lcol+1][lrow]=av.y; As[lcol+2][lrow]=av.z; As[lcol+3][lrow]=av.w;
        float4 wv = make_float4(0.f,0.f,0.f,0.f);
        if (k0 + lcol < DTR)
            wv = *(const float4*)(W + (size_t)(n0 + lrow)*DTR + k0 + lcol);
        Ws[lcol+0][lrow]=wv.x; Ws[lcol+1][lrow]=wv.y; Ws[lcol+2][lrow]=wv.z; Ws[lcol+3][lrow]=wv.w;
        __syncthreads();
        #pragma unroll
        for (int kk = 0; kk < 16; kk++) {
            float4 a = *(const float4*)&As[kk][ty*4];
            float4 w = *(const float4*)&Ws[kk][tx*4];
            float aa[4]={a.x,a.y,a.z,a.w}, ww[4]={w.x,w.y,w.z,w.w};
            #pragma unroll
            for (int i=0;i<4;i++)
                #pragma unroll
                for (int j=0;j<4;j++)
                    acc[i][j] = fmaf(aa[i], ww[j], acc[i][j]);
        }
        __syncthreads();
    }
    #pragma unroll
    for (int i = 0; i < 4; i++) {
        int m = m0 + ty*4 + i;
        if (m < LL) {
            #pragma unroll
            for (int j = 0; j < 4; j++) {
                int n = n0 + tx*4 + j;
                float a = acc[i][j] + dtb[k*DIN + n];
                float sp = fmaxf(a, 0.f) + __logf(1.f + __expf(-fabsf(a)));
                C[(size_t)m*DIN + n] = sp;
            }
        }
    }
}

// ============ selective scan: 8 lanes per (kb,d), fully streaming ==========
__global__ __launch_bounds__(256) void scan_kernel(const float* __restrict__ A_log,
                                                   const float* __restrict__ Dpv)
{
    int gtid = blockIdx.x * 256 + threadIdx.x;
    int gid = gtid >> 3;
    int li  = threadIdx.x & 7;
    if (gid >= KD*BB*DIN) return;
    int kb = gid / DIN;
    int d  = gid - kb * DIN;
    int k  = kb >> 1;

    float A0 = -expf(A_log[((size_t)k*DIN + d)*DS + 2*li]);
    float A1 = -expf(A_log[((size_t)k*DIN + d)*DS + 2*li + 1]);
    float Dv = Dpv[k*DIN + d];

    const float* dT = g_delta + (size_t)kb*LL*DIN + d;
    const float* uT = g_convT + (size_t)kb*LL*DIN + d;
    const float* zT = g_zsT   + (size_t)kb*LL*DIN + d;
    const float* xT = g_xdbl  + (size_t)kb*LL*NE;
    float* yB = g_yT + (size_t)kb*LL*DIN + d;

    float h0 = 0.f, h1 = 0.f;
    float dc[4], uc[4], zc[4]; float2 Bc[4], Cc[4];
    #pragma unroll
    for (int j = 0; j < 4; j++) {
        dc[j] = dT[(size_t)j*DIN]; uc[j] = uT[(size_t)j*DIN]; zc[j] = zT[(size_t)j*DIN];
        Bc[j] = *(const float2*)(xT + (size_t)j*NE + DTR + 2*li);
        Cc[j] = *(const float2*)(xT + (size_t)j*NE + DTR + DS + 2*li);
    }
    for (int t0 = 0; t0 < LL; t0 += 4) {
        float dn[4], un[4], zn[4]; float2 Bn[4], Cn[4];
        int tn = t0 + 4;
        if (tn < LL) {
            #pragma unroll
            for (int j = 0; j < 4; j++) {
                dn[j] = dT[(size_t)(tn+j)*DIN]; un[j] = uT[(size_t)(tn+j)*DIN];
                zn[j] = zT[(size_t)(tn+j)*DIN];
                Bn[j] = *(const float2*)(xT + (size_t)(tn+j)*NE + DTR + 2*li);
                Cn[j] = *(const float2*)(xT + (size_t)(tn+j)*NE + DTR + DS + 2*li);
            }
        } else {
            #pragma unroll
            for (int j = 0; j < 4; j++) {
                dn[j]=un[j]=zn[j]=0.f; Bn[j]=make_float2(0.f,0.f); Cn[j]=make_float2(0.f,0.f);
            }
        }
        #pragma unroll
        for (int j = 0; j < 4; j++) {
            float delta = dc[j], u = uc[j];
            float e0 = __expf(delta * A0);
            float e1 = __expf(delta * A1);
            float du = delta * u;
            h0 = fmaf(e0, h0, du * Bc[j].x);
            h1 = fmaf(e1, h1, du * Bc[j].y);
            float v = fmaf(h0, Cc[j].x, h1 * Cc[j].y);
            v += __shfl_xor_sync(0xffffffffu, v, 4);
            v += __shfl_xor_sync(0xffffffffu, v, 2);
            v += __shfl_xor_sync(0xffffffffu, v, 1);
            if (li == 0)
                yB[(size_t)(t0+j)*DIN] = fmaf(Dv, u, v) * zc[j];
        }
        #pragma unroll
        for (int j = 0; j < 4; j++) { dc[j]=dn[j]; uc[j]=un[j]; zc[j]=zn[j]; Bc[j]=Bn[j]; Cc[j]=Cn[j]; }
    }
}

// ============ fused LN stats + channel-mean partials =======================
__global__ __launch_bounds__(256) void gvec_part() {
    int kb = blockIdx.y; int ch = blockIdx.x;
    int l0 = ch * 28;
    __shared__ float smu[28], srs[28];
    int tid = threadIdx.x;
    int wid = tid >> 5, lane = tid & 31;

    for (int r = wid; r < 28; r += 8) {
        const float4* row = (const float4*)(g_yT + ((size_t)kb*LL + l0 + r)*DIN);
        float s = 0.f, s2 = 0.f;
        #pragma unroll
        for (int i = 0; i < 6; i++) {
            float4 v = row[lane + i*32];
            s += v.x + v.y + v.z + v.w;
            s2 = fmaf(v.x, v.x, s2); s2 = fmaf(v.y, v.y, s2);
            s2 = fmaf(v.z, v.z, s2); s2 = fmaf(v.w, v.w, s2);
        }
        #pragma unroll
        for (int o = 16; o > 0; o >>= 1) {
            s  += __shfl_xor_sync(0xffffffffu, s,  o);
            s2 += __shfl_xor_sync(0xffffffffu, s2, o);
        }
        if (lane == 0) {
            float mu = s * (1.f / DIN);
            float var = s2 * (1.f / DIN) - mu * mu;
            smu[r] = mu;
            srs[r] = rsqrtf(var + 1e-5f);
        }
    }
    __syncthreads();

    int c = tid;
    float a0 = 0.f, a1 = 0.f, a2 = 0.f;
    for (int r = 0; r < 28; r++) {
        float mu = smu[r], rs = srs[r];
        const float* row = g_yT + ((size_t)kb*LL + l0 + r)*DIN;
        a0 = fmaf(row[c      ] - mu, rs, a0);
        a1 = fmaf(row[c + 256] - mu, rs, a1);
        a2 = fmaf(row[c + 512] - mu, rs, a2);
    }
    float* p = g_gpart + ((size_t)kb*28 + ch)*DIN;
    p[c] = a0; p[c+256] = a1; p[c+512] = a2;
}

// ============ attention MLP with fused gvec-final ==========================
__global__ __launch_bounds__(384) void mlp_kernel(const float* __restrict__ ln_g,
                                                  const float* __restrict__ ln_b,
                                                  const float* __restrict__ gr_w,
                                                  const float* __restrict__ gr_b,
                                                  const float* __restrict__ cs_w,
                                                  const float* __restrict__ cs_b) {
    int kb = blockIdx.x;
    __shared__ float gsh[DIN];
    __shared__ float g2[96];
    int tid = threadIdx.x;

    for (int c = tid; c < DIN; c += 384) {
        float s = 0.f;
        #pragma unroll
        for (int ch = 0; ch < 28; ch++) s += g_gpart[((size_t)kb*28 + ch)*DIN + c];
        gsh[c] = fmaf(ln_g[c], s * (1.f / LL), ln_b[c]);
    }
    __syncthreads();

    int oid = tid >> 2, part = tid & 3;
    {
        float acc = 0.f, acc2 = 0.f;
        const float* w = gr_w + (size_t)oid * DIN;
        for (int c = part*192; c < part*192 + 192; c += 2) {
            acc  = fmaf(w[c],   gsh[c],   acc);
            acc2 = fmaf(w[c+1], gsh[c+1], acc2);
        }
        acc += acc2;
        acc += __shfl_xor_sync(0xffffffffu, acc, 1);
        acc += __shfl_xor_sync(0xffffffffu, acc, 2);
        if (part == 0) {
            acc += gr_b[oid];
            g2[oid] = 0.5f * acc * (1.f + erff(acc * 0.70710678118654752f));
        }
    }
    __syncthreads();
    for (int o = tid; o < DIN; o += 384) {
        float acc = cs_b[o];
        const float* w = cs_w + (size_t)o * 96;
        #pragma unroll
        for (int e = 0; e < 96; e++) acc = fmaf(w[e], g2[e], acc);
        g_attn[(size_t)kb * DIN + o] = 1.f / (1.f + __expf(-acc));
    }
}

// ============ combine (inline inverse map) =================================
__global__ void combine_kernel() {
    int idx = blockIdx.x * 256 + threadIdx.x;
    if (idx >= BB*LL*DIN) return;
    int c  = idx % DIN;
    int bl = idx / DIN;
    int b  = bl / LL;
    int l  = bl % LL;
    float s = 0.f;
    #pragma unroll
    for (int k = 0; k < KD; k++) {
        int kb = k * 2 + b;
        int t  = inv_map_f(k, l);
        s = fmaf(g_yT[((size_t)kb*LL + t)*DIN + c], g_attn[(size_t)kb*DIN + c], s);
    }
    g_s[idx] = s;
}

// ============ launch =======================================================
// Launch order chosen so ncu's "-s 5 -c 1" capture lands on scan_kernel (idx 5).
extern "C" void kernel_launch(void* const* d_in, const int* in_sizes, int n_in,
                              void* d_out, int out_size) {
    const float* x          = (const float*)d_in[0];
    const float* in_proj_w  = (const float*)d_in[1];
    const float* conv_w     = (const float*)d_in[2];
    const float* conv_b     = (const float*)d_in[3];
    const float* x_proj_w   = (const float*)d_in[4];
    const float* dt_w       = (const float*)d_in[5];
    const float* dt_b       = (const float*)d_in[6];
    const float* A_log      = (const float*)d_in[7];
    const float* Dp         = (const float*)d_in[8];
    const float* ln_g       = (const float*)d_in[9];
    const float* ln_b       = (const float*)d_in[10];
    const float* gr_w       = (const float*)d_in[11];
    const float* gr_b       = (const float*)d_in[12];
    const float* cs_w       = (const float*)d_in[13];
    const float* cs_b       = (const float*)d_in[14];
    const float* out_proj_w = (const float*)d_in[15];
    float* out = (float*)d_out;

    gemm_in_proj<<<dim3((2*DIN)/64, (MROWS + 127)/128), 256>>>(x, in_proj_w);   // 0
    conv_z_kernel<<<dim3(25, 24, 8), dim3(32, 8)>>>(conv_w, conv_b);            // 1
    gemm_xdbl<<<dim3(KSPLIT, 13, 8), 256>>>(x_proj_w);                          // 2
    xdbl_reduce<<<(KD*BB*LL*NE + 255)/256, 256>>>();                            // 3
    gemm_delta<<<dim3(12, 13, 8), 256>>>(dt_w, dt_b);                           // 4
    scan_kernel<<<(KD*BB*DIN*8 + 255)/256, 256>>>(A_log, Dp);                   // 5 <- profiled
    gvec_part<<<dim3(28, KD*BB), 256>>>();                                      // 6
    mlp_kernel<<<KD*BB, 384>>>(ln_g, ln_b, gr_w, gr_b, cs_w, cs_b);             // 7
    combine_kernel<<<(BB*LL*DIN + 255)/256, 256>>>();                           // 8
    gemm_out_proj<<<dim3(DMQ/64, (MROWS + 127)/128), 256>>>(out_proj_w, out);   // 9
}

// round 15
// speedup vs baseline: 1.0456x; 1.0456x over previous
#include <cuda_runtime.h>
#include <math.h>
#include <stdint.h>

// ---------------- problem constants ----------------
#define KD   4
#define BB   2
#define LL   784
#define DMQ  384
#define DIN  768
#define DS   16
#define DTR  24
#define NE   56
#define MROWS (BB*LL)   // 1568
#define KSPLIT 4

// ---------------- scratch ----------------
__device__ __align__(16) float g_xz   [BB*LL*2*DIN];
__device__ __align__(16) float g_convT[KD*BB*LL*DIN];
__device__ __align__(16) float g_zsT  [KD*BB*LL*DIN];
__device__ __align__(16) float g_xdblp[KSPLIT*KD*BB*LL*NE];
__device__ __align__(16) float g_xdbl [KD*BB*LL*NE];
__device__ __align__(16) float g_delta[KD*BB*LL*DIN];
__device__ __align__(16) float g_yT   [KD*BB*LL*DIN];
__device__ __align__(16) float g_gpart[KD*BB*28*DIN];
__device__ __align__(16) float g_attn [KD*BB*DIN];
__device__ __align__(16) float g_s    [BB*LL*DIN];

// forward scan map: t -> l
__device__ __forceinline__ int scan_map_f(int k, int t) {
    if (k == 0) return t;
    if (k == 1) { int wq = t / 28; int hq = t - wq * 28; return hq * 28 + wq; }
    if (k == 3) t = 783 - t;
    int hg = t / 196; int r  = t - hg * 196;
    int wg = r / 49;  int r2 = r - wg * 49;
    int i  = r2 / 7;  int j  = r2 - i * 7;
    return (hg * 7 + i) * 28 + (wg * 7 + j);
}
// inverse map: l -> t
__device__ __forceinline__ int inv_map_f(int k, int l) {
    if (k == 0) return l;
    if (k == 1) { int lr = l / 28; int lc = l - lr * 28; return lc * 28 + lr; }
    int lr = l / 28, lc = l - (l / 28) * 28;
    int t = (lr / 7) * 196 + (lc / 7) * 49 + (lr % 7) * 7 + (lc % 7);
    return (k == 3) ? 783 - t : t;
}

__device__ __forceinline__ float siluf(float v) { return v / (1.f + __expf(-v)); }

__device__ __forceinline__ float tf32r(float x) {
    uint32_t r;
    asm("cvt.rna.tf32.f32 %0, %1;" : "=r"(r) : "f"(x));
    return __uint_as_float(r);
}

__device__ __forceinline__ void mma_tf32(float* c, const uint32_t* a, const uint32_t* b) {
    asm volatile(
        "mma.sync.aligned.m16n8k8.row.col.f32.tf32.tf32.f32 "
        "{%0,%1,%2,%3}, {%4,%5,%6,%7}, {%8,%9}, {%0,%1,%2,%3};"
        : "+f"(c[0]), "+f"(c[1]), "+f"(c[2]), "+f"(c[3])
        : "r"(a[0]), "r"(a[1]), "r"(a[2]), "r"(a[3]), "r"(b[0]), "r"(b[1]));
}

// ============ tf32 GEMM: C[m][n] = sum_k A[m][k]*W[n][k] ===================
__device__ __forceinline__ void gemm_tf32_body(
    const float* __restrict__ A, const float* __restrict__ W,
    float* __restrict__ C, int M, int N, int K)
{
    __shared__ float As[2][16][136];
    __shared__ float Ws[2][16][72];
    int m0 = blockIdx.y * 128, n0 = blockIdx.x * 64;
    int tid = threadIdx.x, lane = tid & 31, wid = tid >> 5;
    int wm = (wid & 3) * 32, wn = (wid >> 2) * 32;
    int g = lane >> 2, tg = lane & 3;

    int ar = tid >> 1, ak = (tid & 1) * 8;
    int wr = tid >> 2, wk = (tid & 3) * 4;
    const float* Ap = A + (size_t)(m0 + ar) * K + ak;
    const float* Wp = W + (size_t)(n0 + wr) * K + wk;
    bool aval = (m0 + ar) < M;

    {
        float4 v0 = make_float4(0.f,0.f,0.f,0.f), v1 = v0;
        if (aval) { v0 = *(const float4*)Ap; v1 = *(const float4*)(Ap + 4); }
        As[0][ak+0][ar]=tf32r(v0.x); As[0][ak+1][ar]=tf32r(v0.y);
        As[0][ak+2][ar]=tf32r(v0.z); As[0][ak+3][ar]=tf32r(v0.w);
        As[0][ak+4][ar]=tf32r(v1.x); As[0][ak+5][ar]=tf32r(v1.y);
        As[0][ak+6][ar]=tf32r(v1.z); As[0][ak+7][ar]=tf32r(v1.w);
        float4 w = *(const float4*)Wp;
        Ws[0][wk+0][wr]=tf32r(w.x); Ws[0][wk+1][wr]=tf32r(w.y);
        Ws[0][wk+2][wr]=tf32r(w.z); Ws[0][wk+3][wr]=tf32r(w.w);
    }
    __syncthreads();

    float acc[2][4][4] = {};
    int buf = 0;
    for (int k0 = 0; k0 < K; k0 += 16) {
        if (k0 + 16 < K) {
            int nb = buf ^ 1;
            float4 v0 = make_float4(0.f,0.f,0.f,0.f), v1 = v0;
            if (aval) { v0 = *(const float4*)(Ap + k0 + 16); v1 = *(const float4*)(Ap + k0 + 20); }
            As[nb][ak+0][ar]=tf32r(v0.x); As[nb][ak+1][ar]=tf32r(v0.y);
            As[nb][ak+2][ar]=tf32r(v0.z); As[nb][ak+3][ar]=tf32r(v0.w);
            As[nb][ak+4][ar]=tf32r(v1.x); As[nb][ak+5][ar]=tf32r(v1.y);
            As[nb][ak+6][ar]=tf32r(v1.z); As[nb][ak+7][ar]=tf32r(v1.w);
            float4 w = *(const float4*)(Wp + k0 + 16);
            Ws[nb][wk+0][wr]=tf32r(w.x); Ws[nb][wk+1][wr]=tf32r(w.y);
            Ws[nb][wk+2][wr]=tf32r(w.z); Ws[nb][wk+3][wr]=tf32r(w.w);
        }
        #pragma unroll
        for (int ks = 0; ks < 16; ks += 8) {
            uint32_t a[2][4], b[4][2];
            #pragma unroll
            for (int i = 0; i < 2; i++) {
                int mb = wm + i * 16;
                a[i][0] = __float_as_uint(As[buf][ks+tg  ][mb + g    ]);
                a[i][1] = __float_as_uint(As[buf][ks+tg  ][mb + g + 8]);
                a[i][2] = __float_as_uint(As[buf][ks+tg+4][mb + g    ]);
                a[i][3] = __float_as_uint(As[buf][ks+tg+4][mb + g + 8]);
            }
            #pragma unroll
            for (int j = 0; j < 4; j++) {
                int nb2 = wn + j * 8;
                b[j][0] = __float_as_uint(Ws[buf][ks+tg  ][nb2 + g]);
                b[j][1] = __float_as_uint(Ws[buf][ks+tg+4][nb2 + g]);
            }
            #pragma unroll
            for (int i = 0; i < 2; i++)
                #pragma unroll
                for (int j = 0; j < 4; j++)
                    mma_tf32(acc[i][j], a[i], b[j]);
        }
        __syncthreads();
        buf ^= 1;
    }

    #pragma unroll
    for (int i = 0; i < 2; i++) {
        int m = m0 + wm + i * 16 + g;
        #pragma unroll
        for (int j = 0; j < 4; j++) {
            int n = n0 + wn + j * 8 + 2 * tg;
            if (m < M)
                *(float2*)(C + (size_t)m * N + n) = make_float2(acc[i][j][0], acc[i][j][1]);
            if (m + 8 < M)
                *(float2*)(C + (size_t)(m + 8) * N + n) = make_float2(acc[i][j][2], acc[i][j][3]);
        }
    }
}

__global__ __launch_bounds__(256) void gemm_in_proj(const float* __restrict__ A,
                                                    const float* __restrict__ W) {
    gemm_tf32_body(A, W, g_xz, MROWS, 2 * DIN, DMQ);
}
__global__ __launch_bounds__(256) void gemm_out_proj(const float* __restrict__ W,
                                                     float* __restrict__ C) {
    gemm_tf32_body(g_s, W, C, MROWS, DMQ, DIN);
}

// ============ gather + depthwise conv + SiLU, and silu(z) in t-order =======
__global__ void conv_z_kernel(const float* __restrict__ conv_w,
                              const float* __restrict__ conv_b)
{
    int kb = blockIdx.z; int k = kb >> 1; int b = kb & 1;
    int t0 = blockIdx.x * 32; int d0 = blockIdx.y * 32;
    __shared__ float xs[35][33];
    __shared__ float zsm[32][33];
    int tid = threadIdx.y * 32 + threadIdx.x;

    for (int idx = tid; idx < 35*32; idx += 256) {
        int r = idx >> 5; int dd = idx & 31;
        int t = t0 - 3 + r;
        float v = 0.f;
        if (t >= 0 && t < LL) {
            int l = scan_map_f(k, t);
            v = g_xz[((size_t)(b*LL + l))*(2*DIN) + d0 + dd];
        }
        xs[r][dd] = v;
    }
    for (int idx = tid; idx < 32*32; idx += 256) {
        int r = idx >> 5; int dd = idx & 31;
        int t = t0 + r;
        float v = 0.f;
        if (t < LL) {
            int l = scan_map_f(k, t);
            v = g_xz[((size_t)(b*LL + l))*(2*DIN) + DIN + d0 + dd];
        }
        zsm[r][dd] = v;
    }
    __syncthreads();

    int dloc = threadIdx.x;
    int d = d0 + dloc;
    float4 w4 = *(const float4*)(conv_w + ((size_t)k*DIN + d)*4);
    float bset = conv_b[k*DIN + d];
    #pragma unroll
    for (int s = 0; s < 4; s++) {
        int tloc = threadIdx.y * 4 + s;
        int t = t0 + tloc;
        if (t < LL) {
            float acc = bset;
            acc = fmaf(w4.x, xs[tloc+0][dloc], acc);
            acc = fmaf(w4.y, xs[tloc+1][dloc], acc);
            acc = fmaf(w4.z, xs[tloc+2][dloc], acc);
            acc = fmaf(w4.w, xs[tloc+3][dloc], acc);
            size_t off = ((size_t)kb*LL + t)*DIN + d;
            g_convT[off] = siluf(acc);
            g_zsT[off]   = siluf(zsm[tloc][dloc]);
        }
    }
}

// ============ x_dbl GEMM split-K ===========================================
__global__ __launch_bounds__(256) void gemm_xdbl(const float* __restrict__ xpw)
{
    int kb = blockIdx.z; int k = kb >> 1;
    int kc = blockIdx.x;
    const float* A = g_convT + (size_t)kb*LL*DIN;
    const float* W = xpw + (size_t)k*NE*DIN;
    float* C = g_xdblp + (size_t)kc*(KD*BB*LL*NE) + (size_t)kb*LL*NE;
    __shared__ float As[16][68];
    __shared__ float Ws[16][68];
    int m0 = blockIdx.y * 64;
    int tid = threadIdx.x;
    int lrow = tid >> 2; int lcol = (tid & 3)*4;
    int tx = tid & 15, ty = tid >> 4;
    float acc[4][4] = {};
    int kbeg = kc * 192, kend = kbeg + 192;
    for (int k0 = kbeg; k0 < kend; k0 += 16) {
        float4 av = make_float4(0.f,0.f,0.f,0.f);
        int m = m0 + lrow;
        if (m < LL) av = *(const float4*)(A + (size_t)m*DIN + k0 + lcol);
        As[lcol+0][lrow]=av.x; As[lcol+1][lrow]=av.y; As[lcol+2][lrow]=av.z; As[lcol+3][lrow]=av.w;
        float4 wv = make_float4(0.f,0.f,0.f,0.f);
        if (lrow < NE) wv = *(const float4*)(W + (size_t)lrow*DIN + k0 + lcol);
        Ws[lcol+0][lrow]=wv.x; Ws[lcol+1][lrow]=wv.y; Ws[lcol+2][lrow]=wv.z; Ws[lcol+3][lrow]=wv.w;
        __syncthreads();
        #pragma unroll
        for (int kk = 0; kk < 16; kk++) {
            float4 a = *(const float4*)&As[kk][ty*4];
            float4 w = *(const float4*)&Ws[kk][tx*4];
            float aa[4]={a.x,a.y,a.z,a.w}, ww[4]={w.x,w.y,w.z,w.w};
            #pragma unroll
            for (int i=0;i<4;i++)
                #pragma unroll
                for (int j=0;j<4;j++)
                    acc[i][j] = fmaf(aa[i], ww[j], acc[i][j]);
        }
        __syncthreads();
    }
    if (tx < 14) {
        #pragma unroll
        for (int i = 0; i < 4; i++) {
            int m = m0 + ty*4 + i;
            if (m < LL)
                #pragma unroll
                for (int j = 0; j < 4; j++)
                    C[(size_t)m*NE + tx*4 + j] = acc[i][j];
        }
    }
}

__global__ void xdbl_reduce() {
    int idx = blockIdx.x * 256 + threadIdx.x;
    if (idx >= KD*BB*LL*NE) return;
    float s = 0.f;
    #pragma unroll
    for (int kc = 0; kc < KSPLIT; kc++)
        s += g_xdblp[(size_t)kc*(KD*BB*LL*NE) + idx];
    g_xdbl[idx] = s;
}

// ============ delta GEMM + fast softplus ===================================
__global__ __launch_bounds__(256) void gemm_delta(const float* __restrict__ dtw,
                                                  const float* __restrict__ dtb)
{
    int kb = blockIdx.z; int k = kb >> 1;
    const float* A = g_xdbl + (size_t)kb*LL*NE;
    const float* W = dtw + (size_t)k*DIN*DTR;
    float* C = g_delta + (size_t)kb*LL*DIN;
    __shared__ float As[16][68];
    __shared__ float Ws[16][68];
    int m0 = blockIdx.y * 64, n0 = blockIdx.x * 64;
    int tid = threadIdx.x;
    int lrow = tid >> 2; int lcol = (tid & 3)*4;
    int tx = tid & 15, ty = tid >> 4;
    float acc[4][4] = {};
    for (int k0 = 0; k0 < 32; k0 += 16) {
        float4 av = make_float4(0.f,0.f,0.f,0.f);
        int m = m0 + lrow;
        if (m < LL) av = *(const float4*)(A + (size_t)m*NE + k0 + lcol);
        As[lcol+0][lrow]=av.x; As[lcol+1][lrow]=av.y; As[lcol+2][lrow]=av.z; As[lcol+3][lrow]=av.w;
        float4 wv = make_float4(0.f,0.f,0.f,0.f);
        if (k0 + lcol < DTR)
            wv = *(const float4*)(W + (size_t)(n0 + lrow)*DTR + k0 + lcol);
        Ws[lcol+0][lrow]=wv.x; Ws[lcol+1][lrow]=wv.y; Ws[lcol+2][lrow]=wv.z; Ws[lcol+3][lrow]=wv.w;
        __syncthreads();
        #pragma unroll
        for (int kk = 0; kk < 16; kk++) {
            float4 a = *(const float4*)&As[kk][ty*4];
            float4 w = *(const float4*)&Ws[kk][tx*4];
            float aa[4]={a.x,a.y,a.z,a.w}, ww[4]={w.x,w.y,w.z,w.w};
            #pragma unroll
            for (int i=0;i<4;i++)
                #pragma unroll
                for (int j=0;j<4;j++)
                    acc[i][j] = fmaf(aa[i], ww[j], acc[i][j]);
        }
        __syncthreads();
    }
    #pragma unroll
    for (int i = 0; i < 4; i++) {
        int m = m0 + ty*4 + i;
        if (m < LL) {
            #pragma unroll
            for (int j = 0; j < 4; j++) {
                int n = n0 + tx*4 + j;
                float a = acc[i][j] + dtb[k*DIN + n];
                float sp = fmaxf(a, 0.f) + __logf(1.f + __expf(-fabsf(a)));
                C[(size_t)m*DIN + n] = sp;
            }
        }
    }
}

// ============ selective scan: 8 lanes per (kb,d), fully streaming ==========
__global__ __launch_bounds__(256) void scan_kernel(const float* __restrict__ A_log,
                                                   const float* __restrict__ Dpv)
{
    int gtid = blockIdx.x * 256 + threadIdx.x;
    int gid = gtid >> 3;
    int li  = threadIdx.x & 7;
    if (gid >= KD*BB*DIN) return;
    int kb = gid / DIN;
    int d  = gid - kb * DIN;
    int k  = kb >> 1;

    float A0 = -expf(A_log[((size_t)k*DIN + d)*DS + 2*li]);
    float A1 = -expf(A_log[((size_t)k*DIN + d)*DS + 2*li + 1]);
    float Dv = Dpv[k*DIN + d];

    const float* dT = g_delta + (size_t)kb*LL*DIN + d;
    const float* uT = g_convT + (size_t)kb*LL*DIN + d;
    const float* zT = g_zsT   + (size_t)kb*LL*DIN + d;
    const float* xT = g_xdbl  + (size_t)kb*LL*NE;
    float* yB = g_yT + (size_t)kb*LL*DIN + d;

    float h0 = 0.f, h1 = 0.f;
    float dc[4], uc[4], zc[4]; float2 Bc[4], Cc[4];
    #pragma unroll
    for (int j = 0; j < 4; j++) {
        dc[j] = dT[(size_t)j*DIN]; uc[j] = uT[(size_t)j*DIN]; zc[j] = zT[(size_t)j*DIN];
        Bc[j] = *(const float2*)(xT + (size_t)j*NE + DTR + 2*li);
        Cc[j] = *(const float2*)(xT + (size_t)j*NE + DTR + DS + 2*li);
    }
    for (int t0 = 0; t0 < LL; t0 += 4) {
        float dn[4], un[4], zn[4]; float2 Bn[4], Cn[4];
        int tn = t0 + 4;
        if (tn < LL) {
            #pragma unroll
            for (int j = 0; j < 4; j++) {
                dn[j] = dT[(size_t)(tn+j)*DIN]; un[j] = uT[(size_t)(tn+j)*DIN];
                zn[j] = zT[(size_t)(tn+j)*DIN];
                Bn[j] = *(const float2*)(xT + (size_t)(tn+j)*NE + DTR + 2*li);
                Cn[j] = *(const float2*)(xT + (size_t)(tn+j)*NE + DTR + DS + 2*li);
            }
        } else {
            #pragma unroll
            for (int j = 0; j < 4; j++) {
                dn[j]=un[j]=zn[j]=0.f; Bn[j]=make_float2(0.f,0.f); Cn[j]=make_float2(0.f,0.f);
            }
        }
        #pragma unroll
        for (int j = 0; j < 4; j++) {
            float delta = dc[j], u = uc[j];
            float e0 = __expf(delta * A0);
            float e1 = __expf(delta * A1);
            float du = delta * u;
            h0 = fmaf(e0, h0, du * Bc[j].x);
            h1 = fmaf(e1, h1, du * Bc[j].y);
            float v = fmaf(h0, Cc[j].x, h1 * Cc[j].y);
            v += __shfl_xor_sync(0xffffffffu, v, 4);
            v += __shfl_xor_sync(0xffffffffu, v, 2);
            v += __shfl_xor_sync(0xffffffffu, v, 1);
            if (li == 0)
                yB[(size_t)(t0+j)*DIN] = fmaf(Dv, u, v) * zc[j];
        }
        #pragma unroll
        for (int j = 0; j < 4; j++) { dc[j]=dn[j]; uc[j]=un[j]; zc[j]=zn[j]; Bc[j]=Bn[j]; Cc[j]=Cn[j]; }
    }
}

// ============ fused LN stats + channel-mean partials =======================
__global__ __launch_bounds__(256) void gvec_part() {
    int kb = blockIdx.y; int ch = blockIdx.x;
    int l0 = ch * 28;
    __shared__ float smu[28], srs[28];
    int tid = threadIdx.x;
    int wid = tid >> 5, lane = tid & 31;

    for (int r = wid; r < 28; r += 8) {
        const float4* row = (const float4*)(g_yT + ((size_t)kb*LL + l0 + r)*DIN);
        float s = 0.f, s2 = 0.f;
        #pragma unroll
        for (int i = 0; i < 6; i++) {
            float4 v = row[lane + i*32];
            s += v.x + v.y + v.z + v.w;
            s2 = fmaf(v.x, v.x, s2); s2 = fmaf(v.y, v.y, s2);
            s2 = fmaf(v.z, v.z, s2); s2 = fmaf(v.w, v.w, s2);
        }
        #pragma unroll
        for (int o = 16; o > 0; o >>= 1) {
            s  += __shfl_xor_sync(0xffffffffu, s,  o);
            s2 += __shfl_xor_sync(0xffffffffu, s2, o);
        }
        if (lane == 0) {
            float mu = s * (1.f / DIN);
            float var = s2 * (1.f / DIN) - mu * mu;
            smu[r] = mu;
            srs[r] = rsqrtf(var + 1e-5f);
        }
    }
    __syncthreads();

    int c = tid;
    float a0 = 0.f, a1 = 0.f, a2 = 0.f;
    for (int r = 0; r < 28; r++) {
        float mu = smu[r], rs = srs[r];
        const float* row = g_yT + ((size_t)kb*LL + l0 + r)*DIN;
        a0 = fmaf(row[c      ] - mu, rs, a0);
        a1 = fmaf(row[c + 256] - mu, rs, a1);
        a2 = fmaf(row[c + 512] - mu, rs, a2);
    }
    float* p = g_gpart + ((size_t)kb*28 + ch)*DIN;
    p[c] = a0; p[c+256] = a1; p[c+512] = a2;
}

// ============ attention MLP with fused gvec-final ==========================
__global__ __launch_bounds__(384) void mlp_kernel(const float* __restrict__ ln_g,
                                                  const float* __restrict__ ln_b,
                                                  const float* __restrict__ gr_w,
                                                  const float* __restrict__ gr_b,
                                                  const float* __restrict__ cs_w,
                                                  const float* __restrict__ cs_b) {
    int kb = blockIdx.x;
    __shared__ float gsh[DIN];
    __shared__ float g2[96];
    int tid = threadIdx.x;

    for (int c = tid; c < DIN; c += 384) {
        float s = 0.f;
        #pragma unroll
        for (int ch = 0; ch < 28; ch++) s += g_gpart[((size_t)kb*28 + ch)*DIN + c];
        gsh[c] = fmaf(ln_g[c], s * (1.f / LL), ln_b[c]);
    }
    __syncthreads();

    int oid = tid >> 2, part = tid & 3;
    {
        float acc = 0.f, acc2 = 0.f;
        const float* w = gr_w + (size_t)oid * DIN;
        for (int c = part*192; c < part*192 + 192; c += 2) {
            acc  = fmaf(w[c],   gsh[c],   acc);
            acc2 = fmaf(w[c+1], gsh[c+1], acc2);
        }
        acc += acc2;
        acc += __shfl_xor_sync(0xffffffffu, acc, 1);
        acc += __shfl_xor_sync(0xffffffffu, acc, 2);
        if (part == 0) {
            acc += gr_b[oid];
            g2[oid] = 0.5f * acc * (1.f + erff(acc * 0.70710678118654752f));
        }
    }
    __syncthreads();
    for (int o = tid; o < DIN; o += 384) {
        float acc = cs_b[o];
        const float* w = cs_w + (size_t)o * 96;
        #pragma unroll
        for (int e = 0; e < 96; e++) acc = fmaf(w[e], g2[e], acc);
        g_attn[(size_t)kb * DIN + o] = 1.f / (1.f + __expf(-acc));
    }
}

// ============ combine (inline inverse map) =================================
__global__ void combine_kernel() {
    int idx = blockIdx.x * 256 + threadIdx.x;
    if (idx >= BB*LL*DIN) return;
    int c  = idx % DIN;
    int bl = idx / DIN;
    int b  = bl / LL;
    int l  = bl % LL;
    float s = 0.f;
    #pragma unroll
    for (int k = 0; k < KD; k++) {
        int kb = k * 2 + b;
        int t  = inv_map_f(k, l);
        s = fmaf(g_yT[((size_t)kb*LL + t)*DIN + c], g_attn[(size_t)kb*DIN + c], s);
    }
    g_s[idx] = s;
}

// ============ launch =======================================================
// Launch order chosen so ncu's "-s 5 -c 1" capture lands on scan_kernel (idx 5).
extern "C" void kernel_launch(void* const* d_in, const int* in_sizes, int n_in,
                              void* d_out, int out_size) {
    const float* x          = (const float*)d_in[0];
    const float* in_proj_w  = (const float*)d_in[1];
    const float* conv_w     = (const float*)d_in[2];
    const float* conv_b     = (const float*)d_in[3];
    const float* x_proj_w   = (const float*)d_in[4];
    const float* dt_w       = (const float*)d_in[5];
    const float* dt_b       = (const float*)d_in[6];
    const float* A_log      = (const float*)d_in[7];
    const float* Dp         = (const float*)d_in[8];
    const float* ln_g       = (const float*)d_in[9];
    const float* ln_b       = (const float*)d_in[10];
    const float* gr_w       = (const float*)d_in[11];
    const float* gr_b       = (const float*)d_in[12];
    const float* cs_w       = (const float*)d_in[13];
    const float* cs_b       = (const float*)d_in[14];
    const float* out_proj_w = (const float*)d_in[15];
    float* out = (float*)d_out;

    gemm_in_proj<<<dim3((2*DIN)/64, (MROWS + 127)/128), 256>>>(x, in_proj_w);   // 0
    conv_z_kernel<<<dim3(25, 24, 8), dim3(32, 8)>>>(conv_w, conv_b);            // 1
    gemm_xdbl<<<dim3(KSPLIT, 13, 8), 256>>>(x_proj_w);                          // 2
    xdbl_reduce<<<(KD*BB*LL*NE + 255)/256, 256>>>();                            // 3
    gemm_delta<<<dim3(12, 13, 8), 256>>>(dt_w, dt_b);                           // 4
    scan_kernel<<<(KD*BB*DIN*8 + 255)/256, 256>>>(A_log, Dp);                   // 5 <- profiled
    gvec_part<<<dim3(28, KD*BB), 256>>>();                                      // 6
    mlp_kernel<<<KD*BB, 384>>>(ln_g, ln_b, gr_w, gr_b, cs_w, cs_b);             // 7
    combine_kernel<<<(BB*LL*DIN + 255)/256, 256>>>();                           // 8
    gemm_out_proj<<<dim3(DMQ/64, (MROWS + 127)/128), 256>>>(out_proj_w, out);   // 9
}

// round 16
// speedup vs baseline: 1.0458x; 1.0002x over previous
#include <cuda_runtime.h>
#include <math.h>
#include <stdint.h>

// ---------------- problem constants ----------------
#define KD   4
#define BB   2
#define LL   784
#define DMQ  384
#define DIN  768
#define DS   16
#define DTR  24
#define NE   56
#define MROWS (BB*LL)   // 1568
#define KSPLIT 4

// ---------------- scratch ----------------
__device__ __align__(16) float g_xz   [BB*LL*2*DIN];
__device__ __align__(16) float g_convT[KD*BB*LL*DIN];
__device__ __align__(16) float g_zsT  [KD*BB*LL*DIN];
__device__ __align__(16) float g_xdblp[KSPLIT*KD*BB*LL*NE];
__device__ __align__(16) float g_xdbl [KD*BB*LL*NE];
__device__ __align__(16) float g_delta[KD*BB*LL*DIN];
__device__ __align__(16) float g_yT   [KD*BB*LL*DIN];
__device__ __align__(16) float g_gpart[KD*BB*28*DIN];
__device__ __align__(16) float g_attn [KD*BB*DIN];
__device__ __align__(16) float g_s    [BB*LL*DIN];

// forward scan map: t -> l
__device__ __forceinline__ int scan_map_f(int k, int t) {
    if (k == 0) return t;
    if (k == 1) { int wq = t / 28; int hq = t - wq * 28; return hq * 28 + wq; }
    if (k == 3) t = 783 - t;
    int hg = t / 196; int r  = t - hg * 196;
    int wg = r / 49;  int r2 = r - wg * 49;
    int i  = r2 / 7;  int j  = r2 - i * 7;
    return (hg * 7 + i) * 28 + (wg * 7 + j);
}
// inverse map: l -> t
__device__ __forceinline__ int inv_map_f(int k, int l) {
    if (k == 0) return l;
    if (k == 1) { int lr = l / 28; int lc = l - lr * 28; return lc * 28 + lr; }
    int lr = l / 28, lc = l - (l / 28) * 28;
    int t = (lr / 7) * 196 + (lc / 7) * 49 + (lr % 7) * 7 + (lc % 7);
    return (k == 3) ? 783 - t : t;
}

__device__ __forceinline__ float siluf(float v) { return v / (1.f + __expf(-v)); }

__device__ __forceinline__ float tf32r(float x) {
    uint32_t r;
    asm("cvt.rna.tf32.f32 %0, %1;" : "=r"(r) : "f"(x));
    return __uint_as_float(r);
}

__device__ __forceinline__ void mma_tf32(float* c, const uint32_t* a, const uint32_t* b) {
    asm volatile(
        "mma.sync.aligned.m16n8k8.row.col.f32.tf32.tf32.f32 "
        "{%0,%1,%2,%3}, {%4,%5,%6,%7}, {%8,%9}, {%0,%1,%2,%3};"
        : "+f"(c[0]), "+f"(c[1]), "+f"(c[2]), "+f"(c[3])
        : "r"(a[0]), "r"(a[1]), "r"(a[2]), "r"(a[3]), "r"(b[0]), "r"(b[1]));
}

// ============ tf32 GEMM: C[m][n] = sum_k A[m][k]*W[n][k] ===================
__device__ __forceinline__ void gemm_tf32_body(
    const float* __restrict__ A, const float* __restrict__ W,
    float* __restrict__ C, int M, int N, int K)
{
    __shared__ float As[2][16][136];
    __shared__ float Ws[2][16][72];
    int m0 = blockIdx.y * 128, n0 = blockIdx.x * 64;
    int tid = threadIdx.x, lane = tid & 31, wid = tid >> 5;
    int wm = (wid & 3) * 32, wn = (wid >> 2) * 32;
    int g = lane >> 2, tg = lane & 3;

    int ar = tid >> 1, ak = (tid & 1) * 8;
    int wr = tid >> 2, wk = (tid & 3) * 4;
    const float* Ap = A + (size_t)(m0 + ar) * K + ak;
    const float* Wp = W + (size_t)(n0 + wr) * K + wk;
    bool aval = (m0 + ar) < M;

    {
        float4 v0 = make_float4(0.f,0.f,0.f,0.f), v1 = v0;
        if (aval) { v0 = *(const float4*)Ap; v1 = *(const float4*)(Ap + 4); }
        As[0][ak+0][ar]=tf32r(v0.x); As[0][ak+1][ar]=tf32r(v0.y);
        As[0][ak+2][ar]=tf32r(v0.z); As[0][ak+3][ar]=tf32r(v0.w);
        As[0][ak+4][ar]=tf32r(v1.x); As[0][ak+5][ar]=tf32r(v1.y);
        As[0][ak+6][ar]=tf32r(v1.z); As[0][ak+7][ar]=tf32r(v1.w);
        float4 w = *(const float4*)Wp;
        Ws[0][wk+0][wr]=tf32r(w.x); Ws[0][wk+1][wr]=tf32r(w.y);
        Ws[0][wk+2][wr]=tf32r(w.z); Ws[0][wk+3][wr]=tf32r(w.w);
    }
    __syncthreads();

    float acc[2][4][4] = {};
    int buf = 0;
    for (int k0 = 0; k0 < K; k0 += 16) {
        if (k0 + 16 < K) {
            int nb = buf ^ 1;
            float4 v0 = make_float4(0.f,0.f,0.f,0.f), v1 = v0;
            if (aval) { v0 = *(const float4*)(Ap + k0 + 16); v1 = *(const float4*)(Ap + k0 + 20); }
            As[nb][ak+0][ar]=tf32r(v0.x); As[nb][ak+1][ar]=tf32r(v0.y);
            As[nb][ak+2][ar]=tf32r(v0.z); As[nb][ak+3][ar]=tf32r(v0.w);
            As[nb][ak+4][ar]=tf32r(v1.x); As[nb][ak+5][ar]=tf32r(v1.y);
            As[nb][ak+6][ar]=tf32r(v1.z); As[nb][ak+7][ar]=tf32r(v1.w);
            float4 w = *(const float4*)(Wp + k0 + 16);
            Ws[nb][wk+0][wr]=tf32r(w.x); Ws[nb][wk+1][wr]=tf32r(w.y);
            Ws[nb][wk+2][wr]=tf32r(w.z); Ws[nb][wk+3][wr]=tf32r(w.w);
        }
        #pragma unroll
        for (int ks = 0; ks < 16; ks += 8) {
            uint32_t a[2][4], b[4][2];
            #pragma unroll
            for (int i = 0; i < 2; i++) {
                int mb = wm + i * 16;
                a[i][0] = __float_as_uint(As[buf][ks+tg  ][mb + g    ]);
                a[i][1] = __float_as_uint(As[buf][ks+tg  ][mb + g + 8]);
                a[i][2] = __float_as_uint(As[buf][ks+tg+4][mb + g    ]);
                a[i][3] = __float_as_uint(As[buf][ks+tg+4][mb + g + 8]);
            }
            #pragma unroll
            for (int j = 0; j < 4; j++) {
                int nb2 = wn + j * 8;
                b[j][0] = __float_as_uint(Ws[buf][ks+tg  ][nb2 + g]);
                b[j][1] = __float_as_uint(Ws[buf][ks+tg+4][nb2 + g]);
            }
            #pragma unroll
            for (int i = 0; i < 2; i++)
                #pragma unroll
                for (int j = 0; j < 4; j++)
                    mma_tf32(acc[i][j], a[i], b[j]);
        }
        __syncthreads();
        buf ^= 1;
    }

    #pragma unroll
    for (int i = 0; i < 2; i++) {
        int m = m0 + wm + i * 16 + g;
        #pragma unroll
        for (int j = 0; j < 4; j++) {
            int n = n0 + wn + j * 8 + 2 * tg;
            if (m < M)
                *(float2*)(C + (size_t)m * N + n) = make_float2(acc[i][j][0], acc[i][j][1]);
            if (m + 8 < M)
                *(float2*)(C + (size_t)(m + 8) * N + n) = make_float2(acc[i][j][2], acc[i][j][3]);
        }
    }
}

__global__ __launch_bounds__(256) void gemm_in_proj(const float* __restrict__ A,
                                                    const float* __restrict__ W) {
    gemm_tf32_body(A, W, g_xz, MROWS, 2 * DIN, DMQ);
}
__global__ __launch_bounds__(256) void gemm_out_proj(const float* __restrict__ W,
                                                     float* __restrict__ C) {
    gemm_tf32_body(g_s, W, C, MROWS, DMQ, DIN);
}

// ============ gather + depthwise conv + SiLU, and silu(z) in t-order =======
__global__ void conv_z_kernel(const float* __restrict__ conv_w,
                              const float* __restrict__ conv_b)
{
    int kb = blockIdx.z; int k = kb >> 1; int b = kb & 1;
    int t0 = blockIdx.x * 32; int d0 = blockIdx.y * 32;
    __shared__ float xs[35][33];
    __shared__ float zsm[32][33];
    int tid = threadIdx.y * 32 + threadIdx.x;

    for (int idx = tid; idx < 35*32; idx += 256) {
        int r = idx >> 5; int dd = idx & 31;
        int t = t0 - 3 + r;
        float v = 0.f;
        if (t >= 0 && t < LL) {
            int l = scan_map_f(k, t);
            v = g_xz[((size_t)(b*LL + l))*(2*DIN) + d0 + dd];
        }
        xs[r][dd] = v;
    }
    for (int idx = tid; idx < 32*32; idx += 256) {
        int r = idx >> 5; int dd = idx & 31;
        int t = t0 + r;
        float v = 0.f;
        if (t < LL) {
            int l = scan_map_f(k, t);
            v = g_xz[((size_t)(b*LL + l))*(2*DIN) + DIN + d0 + dd];
        }
        zsm[r][dd] = v;
    }
    __syncthreads();

    int dloc = threadIdx.x;
    int d = d0 + dloc;
    float4 w4 = *(const float4*)(conv_w + ((size_t)k*DIN + d)*4);
    float bset = conv_b[k*DIN + d];
    #pragma unroll
    for (int s = 0; s < 4; s++) {
        int tloc = threadIdx.y * 4 + s;
        int t = t0 + tloc;
        if (t < LL) {
            float acc = bset;
            acc = fmaf(w4.x, xs[tloc+0][dloc], acc);
            acc = fmaf(w4.y, xs[tloc+1][dloc], acc);
            acc = fmaf(w4.z, xs[tloc+2][dloc], acc);
            acc = fmaf(w4.w, xs[tloc+3][dloc], acc);
            size_t off = ((size_t)kb*LL + t)*DIN + d;
            g_convT[off] = siluf(acc);
            g_zsT[off]   = siluf(zsm[tloc][dloc]);
        }
    }
}

// ============ x_dbl GEMM split-K ===========================================
__global__ __launch_bounds__(256) void gemm_xdbl(const float* __restrict__ xpw)
{
    int kb = blockIdx.z; int k = kb >> 1;
    int kc = blockIdx.x;
    const float* A = g_convT + (size_t)kb*LL*DIN;
    const float* W = xpw + (size_t)k*NE*DIN;
    float* C = g_xdblp + (size_t)kc*(KD*BB*LL*NE) + (size_t)kb*LL*NE;
    __shared__ float As[16][68];
    __shared__ float Ws[16][68];
    int m0 = blockIdx.y * 64;
    int tid = threadIdx.x;
    int lrow = tid >> 2; int lcol = (tid & 3)*4;
    int tx = tid & 15, ty = tid >> 4;
    float acc[4][4] = {};
    int kbeg = kc * 192, kend = kbeg + 192;
    for (int k0 = kbeg; k0 < kend; k0 += 16) {
        float4 av = make_float4(0.f,0.f,0.f,0.f);
        int m = m0 + lrow;
        if (m < LL) av = *(const float4*)(A + (size_t)m*DIN + k0 + lcol);
        As[lcol+0][lrow]=av.x; As[lcol+1][lrow]=av.y; As[lcol+2][lrow]=av.z; As[lcol+3][lrow]=av.w;
        float4 wv = make_float4(0.f,0.f,0.f,0.f);
        if (lrow < NE) wv = *(const float4*)(W + (size_t)lrow*DIN + k0 + lcol);
        Ws[lcol+0][lrow]=wv.x; Ws[lcol+1][lrow]=wv.y; Ws[lcol+2][lrow]=wv.z; Ws[lcol+3][lrow]=wv.w;
        __syncthreads();
        #pragma unroll
        for (int kk = 0; kk < 16; kk++) {
            float4 a = *(const float4*)&As[kk][ty*4];
            float4 w = *(const float4*)&Ws[kk][tx*4];
            float aa[4]={a.x,a.y,a.z,a.w}, ww[4]={w.x,w.y,w.z,w.w};
            #pragma unroll
            for (int i=0;i<4;i++)
                #pragma unroll
                for (int j=0;j<4;j++)
                    acc[i][j] = fmaf(aa[i], ww[j], acc[i][j]);
        }
        __syncthreads();
    }
    if (tx < 14) {
        #pragma unroll
        for (int i = 0; i < 4; i++) {
            int m = m0 + ty*4 + i;
            if (m < LL)
                #pragma unroll
                for (int j = 0; j < 4; j++)
                    C[(size_t)m*NE + tx*4 + j] = acc[i][j];
        }
    }
}

__global__ void xdbl_reduce() {
    int idx = blockIdx.x * 256 + threadIdx.x;
    if (idx >= KD*BB*LL*NE) return;
    float s = 0.f;
    #pragma unroll
    for (int kc = 0; kc < KSPLIT; kc++)
        s += g_xdblp[(size_t)kc*(KD*BB*LL*NE) + idx];
    g_xdbl[idx] = s;
}

// ============ delta GEMM + fast softplus ===================================
__global__ __launch_bounds__(256) void gemm_delta(const float* __restrict__ dtw,
                                                  const float* __restrict__ dtb)
{
    int kb = blockIdx.z; int k = kb >> 1;
    const float* A = g_xdbl + (size_t)kb*LL*NE;
    const float* W = dtw + (size_t)k*DIN*DTR;
    float* C = g_delta + (size_t)kb*LL*DIN;
    __shared__ float As[16][68];
    __shared__ float Ws[16][68];
    int m0 = blockIdx.y * 64, n0 = blockIdx.x * 64;
    int tid = threadIdx.x;
    int lrow = tid >> 2; int lcol = (tid & 3)*4;
    int tx = tid & 15, ty = tid >> 4;
    float acc[4][4] = {};
    for (int k0 = 0; k0 < 32; k0 += 16) {
        float4 av = make_float4(0.f,0.f,0.f,0.f);
        int m = m0 + lrow;
        if (m < LL) av = *(const float4*)(A + (size_t)m*NE + k0 + lcol);
        As[lcol+0][lrow]=av.x; As[lcol+1][lrow]=av.y; As[lcol+2][lrow]=av.z; As[lcol+3][lrow]=av.w;
        float4 wv = make_float4(0.f,0.f,0.f,0.f);
        if (k0 + lcol < DTR)
            wv = *(const float4*)(W + (size_t)(n0 + lrow)*DTR + k0 + lcol);
        Ws[lcol+0][lrow]=wv.x; Ws[lcol+1][lrow]=wv.y; Ws[lcol+2][lrow]=wv.z; Ws[lcol+3][lrow]=wv.w;
        __syncthreads();
        #pragma unroll
        for (int kk = 0; kk < 16; kk++) {
            float4 a = *(const float4*)&As[kk][ty*4];
            float4 w = *(const float4*)&Ws[kk][tx*4];
            float aa[4]={a.x,a.y,a.z,a.w}, ww[4]={w.x,w.y,w.z,w.w};
            #pragma unroll
            for (int i=0;i<4;i++)
                #pragma unroll
                for (int j=0;j<4;j++)
                    acc[i][j] = fmaf(aa[i], ww[j], acc[i][j]);
        }
        __syncthreads();
    }
    #pragma unroll
    for (int i = 0; i < 4; i++) {
        int m = m0 + ty*4 + i;
        if (m < LL) {
            #pragma unroll
            for (int j = 0; j < 4; j++) {
                int n = n0 + tx*4 + j;
                float a = acc[i][j] + dtb[k*DIN + n];
                float sp = fmaxf(a, 0.f) + __logf(1.f + __expf(-fabsf(a)));
                C[(size_t)m*DIN + n] = sp;
            }
        }
    }
}

// ============ selective scan: 8 lanes per (kb,d), fully streaming ==========
__global__ __launch_bounds__(256) void scan_kernel(const float* __restrict__ A_log,
                                                   const float* __restrict__ Dpv)
{
    int gtid = blockIdx.x * 256 + threadIdx.x;
    int gid = gtid >> 3;
    int li  = threadIdx.x & 7;
    if (gid >= KD*BB*DIN) return;
    int kb = gid / DIN;
    int d  = gid - kb * DIN;
    int k  = kb >> 1;

    float A0 = -expf(A_log[((size_t)k*DIN + d)*DS + 2*li]);
    float A1 = -expf(A_log[((size_t)k*DIN + d)*DS + 2*li + 1]);
    float Dv = Dpv[k*DIN + d];

    const float* dT = g_delta + (size_t)kb*LL*DIN + d;
    const float* uT = g_convT + (size_t)kb*LL*DIN + d;
    const float* zT = g_zsT   + (size_t)kb*LL*DIN + d;
    const float* xT = g_xdbl  + (size_t)kb*LL*NE;
    float* yB = g_yT + (size_t)kb*LL*DIN + d;

    float h0 = 0.f, h1 = 0.f;
    float dc[4], uc[4], zc[4]; float2 Bc[4], Cc[4];
    #pragma unroll
    for (int j = 0; j < 4; j++) {
        dc[j] = dT[(size_t)j*DIN]; uc[j] = uT[(size_t)j*DIN]; zc[j] = zT[(size_t)j*DIN];
        Bc[j] = *(const float2*)(xT + (size_t)j*NE + DTR + 2*li);
        Cc[j] = *(const float2*)(xT + (size_t)j*NE + DTR + DS + 2*li);
    }
    for (int t0 = 0; t0 < LL; t0 += 4) {
        float dn[4], un[4], zn[4]; float2 Bn[4], Cn[4];
        int tn = t0 + 4;
        if (tn < LL) {
            #pragma unroll
            for (int j = 0; j < 4; j++) {
                dn[j] = dT[(size_t)(tn+j)*DIN]; un[j] = uT[(size_t)(tn+j)*DIN];
                zn[j] = zT[(size_t)(tn+j)*DIN];
                Bn[j] = *(const float2*)(xT + (size_t)(tn+j)*NE + DTR + 2*li);
                Cn[j] = *(const float2*)(xT + (size_t)(tn+j)*NE + DTR + DS + 2*li);
            }
        } else {
            #pragma unroll
            for (int j = 0; j < 4; j++) {
                dn[j]=un[j]=zn[j]=0.f; Bn[j]=make_float2(0.f,0.f); Cn[j]=make_float2(0.f,0.f);
            }
        }
        #pragma unroll
        for (int j = 0; j < 4; j++) {
            float delta = dc[j], u = uc[j];
            float e0 = __expf(delta * A0);
            float e1 = __expf(delta * A1);
            float du = delta * u;
            h0 = fmaf(e0, h0, du * Bc[j].x);
            h1 = fmaf(e1, h1, du * Bc[j].y);
            float v = fmaf(h0, Cc[j].x, h1 * Cc[j].y);
            v += __shfl_xor_sync(0xffffffffu, v, 4);
            v += __shfl_xor_sync(0xffffffffu, v, 2);
            v += __shfl_xor_sync(0xffffffffu, v, 1);
            if (li == 0)
                yB[(size_t)(t0+j)*DIN] = fmaf(Dv, u, v) * zc[j];
        }
        #pragma unroll
        for (int j = 0; j < 4; j++) { dc[j]=dn[j]; uc[j]=un[j]; zc[j]=zn[j]; Bc[j]=Bn[j]; Cc[j]=Cn[j]; }
    }
}

// ============ fused LN stats + channel-mean partials =======================
__global__ __launch_bounds__(256) void gvec_part() {
    int kb = blockIdx.y; int ch = blockIdx.x;
    int l0 = ch * 28;
    __shared__ float smu[28], srs[28];
    int tid = threadIdx.x;
    int wid = tid >> 5, lane = tid & 31;

    for (int r = wid; r < 28; r += 8) {
        const float4* row = (const float4*)(g_yT + ((size_t)kb*LL + l0 + r)*DIN);
        float s = 0.f, s2 = 0.f;
        #pragma unroll
        for (int i = 0; i < 6; i++) {
            float4 v = row[lane + i*32];
            s += v.x + v.y + v.z + v.w;
            s2 = fmaf(v.x, v.x, s2); s2 = fmaf(v.y, v.y, s2);
            s2 = fmaf(v.z, v.z, s2); s2 = fmaf(v.w, v.w, s2);
        }
        #pragma unroll
        for (int o = 16; o > 0; o >>= 1) {
            s  += __shfl_xor_sync(0xffffffffu, s,  o);
            s2 += __shfl_xor_sync(0xffffffffu, s2, o);
        }
        if (lane == 0) {
            float mu = s * (1.f / DIN);
            float var = s2 * (1.f / DIN) - mu * mu;
            smu[r] = mu;
            srs[r] = rsqrtf(var + 1e-5f);
        }
    }
    __syncthreads();

    int c = tid;
    float a0 = 0.f, a1 = 0.f, a2 = 0.f;
    for (int r = 0; r < 28; r++) {
        float mu = smu[r], rs = srs[r];
        const float* row = g_yT + ((size_t)kb*LL + l0 + r)*DIN;
        a0 = fmaf(row[c      ] - mu, rs, a0);
        a1 = fmaf(row[c + 256] - mu, rs, a1);
        a2 = fmaf(row[c + 512] - mu, rs, a2);
    }
    float* p = g_gpart + ((size_t)kb*28 + ch)*DIN;
    p[c] = a0; p[c+256] = a1; p[c+512] = a2;
}

// ============ attention MLP with fused gvec-final ==========================
__global__ __launch_bounds__(384) void mlp_kernel(const float* __restrict__ ln_g,
                                                  const float* __restrict__ ln_b,
                                                  const float* __restrict__ gr_w,
                                                  const float* __restrict__ gr_b,
                                                  const float* __restrict__ cs_w,
                                                  const float* __restrict__ cs_b) {
    int kb = blockIdx.x;
    __shared__ float gsh[DIN];
    __shared__ float g2[96];
    int tid = threadIdx.x;

    for (int c = tid; c < DIN; c += 384) {
        float s = 0.f;
        #pragma unroll
        for (int ch = 0; ch < 28; ch++) s += g_gpart[((size_t)kb*28 + ch)*DIN + c];
        gsh[c] = fmaf(ln_g[c], s * (1.f / LL), ln_b[c]);
    }
    __syncthreads();

    int oid = tid >> 2, part = tid & 3;
    {
        float acc = 0.f, acc2 = 0.f;
        const float* w = gr_w + (size_t)oid * DIN;
        for (int c = part*192; c < part*192 + 192; c += 2) {
            acc  = fmaf(w[c],   gsh[c],   acc);
            acc2 = fmaf(w[c+1], gsh[c+1], acc2);
        }
        acc += acc2;
        acc += __shfl_xor_sync(0xffffffffu, acc, 1);
        acc += __shfl_xor_sync(0xffffffffu, acc, 2);
        if (part == 0) {
            acc += gr_b[oid];
            g2[oid] = 0.5f * acc * (1.f + erff(acc * 0.70710678118654752f));
        }
    }
    __syncthreads();
    for (int o = tid; o < DIN; o += 384) {
        float acc = cs_b[o];
        const float* w = cs_w + (size_t)o * 96;
        #pragma unroll
        for (int e = 0; e < 96; e++) acc = fmaf(w[e], g2[e], acc);
        g_attn[(size_t)kb * DIN + o] = 1.f / (1.f + __expf(-acc));
    }
}

// ============ combine (inline inverse map) =================================
__global__ void combine_kernel() {
    int idx = blockIdx.x * 256 + threadIdx.x;
    if (idx >= BB*LL*DIN) return;
    int c  = idx % DIN;
    int bl = idx / DIN;
    int b  = bl / LL;
    int l  = bl % LL;
    float s = 0.f;
    #pragma unroll
    for (int k = 0; k < KD; k++) {
        int kb = k * 2 + b;
        int t  = inv_map_f(k, l);
        s = fmaf(g_yT[((size_t)kb*LL + t)*DIN + c], g_attn[(size_t)kb*DIN + c], s);
    }
    g_s[idx] = s;
}

// ============ launch =======================================================
// Launch order chosen so ncu's "-s 5 -c 1" capture lands on scan_kernel (idx 5).
extern "C" void kernel_launch(void* const* d_in, const int* in_sizes, int n_in,
                              void* d_out, int out_size) {
    const float* x          = (const float*)d_in[0];
    const float* in_proj_w  = (const float*)d_in[1];
    const float* conv_w     = (const float*)d_in[2];
    const float* conv_b     = (const float*)d_in[3];
    const float* x_proj_w   = (const float*)d_in[4];
    const float* dt_w       = (const float*)d_in[5];
    const float* dt_b       = (const float*)d_in[6];
    const float* A_log      = (const float*)d_in[7];
    const float* Dp         = (const float*)d_in[8];
    const float* ln_g       = (const float*)d_in[9];
    const float* ln_b       = (const float*)d_in[10];
    const float* gr_w       = (const float*)d_in[11];
    const float* gr_b       = (const float*)d_in[12];
    const float* cs_w       = (const float*)d_in[13];
    const float* cs_b       = (const float*)d_in[14];
    const float* out_proj_w = (const float*)d_in[15];
    float* out = (float*)d_out;

    gemm_in_proj<<<dim3((2*DIN)/64, (MROWS + 127)/128), 256>>>(x, in_proj_w);   // 0
    conv_z_kernel<<<dim3(25, 24, 8), dim3(32, 8)>>>(conv_w, conv_b);            // 1
    gemm_xdbl<<<dim3(KSPLIT, 13, 8), 256>>>(x_proj_w);                          // 2
    xdbl_reduce<<<(KD*BB*LL*NE + 255)/256, 256>>>();                            // 3
    gemm_delta<<<dim3(12, 13, 8), 256>>>(dt_w, dt_b);                           // 4
    scan_kernel<<<(KD*BB*DIN*8 + 255)/256, 256>>>(A_log, Dp);                   // 5 <- profiled
    gvec_part<<<dim3(28, KD*BB), 256>>>();                                      // 6
    mlp_kernel<<<KD*BB, 384>>>(ln_g, ln_b, gr_w, gr_b, cs_w, cs_b);             // 7
    combine_kernel<<<(BB*LL*DIN + 255)/256, 256>>>();                           // 8
    gemm_out_proj<<<dim3(DMQ/64, (MROWS + 127)/128), 256>>>(out_proj_w, out);   // 9
}